// round 16
// baseline (speedup 1.0000x reference)
#include <cuda_runtime.h>
#include <cuda_fp16.h>
#include <math.h>
#include <stdint.h>

// Problem constants
#define NTOK   4096
#define DMODEL 1024
#define DICT   16384
#define TOPK   8
#define TOPC   16      // candidates kept before fp32 rescore

// ---------------------------------------------------------------------------
// Scratch (__device__ globals; no allocation allowed)
// ---------------------------------------------------------------------------
__device__ __half g_xh[(size_t)NTOK * DMODEL];        // 8 MB
__device__ __half g_wh[(size_t)DICT * DMODEL];        // 32 MB
__device__ __half g_ch[(size_t)NTOK * DICT];          // 128 MB (f16 coeffs)
__device__ int   g_cand[NTOK * TOPC];
__device__ float g_tokloss[NTOK];

// ---------------------------------------------------------------------------
// PTX helpers (sm_80-level; legal at virtual arch compute_103)
// ---------------------------------------------------------------------------
__device__ __forceinline__ uint32_t smem_to_u32(const void* p) {
    uint32_t a;
    asm("{ .reg .u64 t; cvta.to.shared.u64 t, %1; cvt.u32.u64 %0, t; }"
        : "=r"(a) : "l"(p));
    return a;
}
__device__ __forceinline__ void cp_async16(uint32_t dst, const void* src) {
    asm volatile("cp.async.cg.shared.global [%0], [%1], 16;" :: "r"(dst), "l"(src));
}
#define CP_COMMIT() asm volatile("cp.async.commit_group;" ::: "memory")
#define CP_WAIT(n)  asm volatile("cp.async.wait_group %0;" :: "n"(n) : "memory")

__device__ __forceinline__ void ldsm_x4(uint32_t* r, uint32_t addr) {
    asm volatile("ldmatrix.sync.aligned.m8n8.x4.shared.b16 {%0,%1,%2,%3}, [%4];"
        : "=r"(r[0]), "=r"(r[1]), "=r"(r[2]), "=r"(r[3]) : "r"(addr));
}
// f16 x f16 -> f16 accumulate (D,C are 2 regs of f16x2)
__device__ __forceinline__ void mma_f16acc(uint32_t* d, const uint32_t* a,
                                           uint32_t b0, uint32_t b1) {
    asm volatile("mma.sync.aligned.m16n8k16.row.col.f16.f16.f16.f16 "
        "{%0,%1}, {%2,%3,%4,%5}, {%6,%7}, {%0,%1};"
        : "+r"(d[0]), "+r"(d[1])
        : "r"(a[0]), "r"(a[1]), "r"(a[2]), "r"(a[3]),
          "r"(b0), "r"(b1));
}

// ---------------------------------------------------------------------------
// Kernel 0: fp32 -> f16 conversion
// ---------------------------------------------------------------------------
__global__ __launch_bounds__(256)
void conv_kernel(const float* __restrict__ in, __half* __restrict__ out, int n4) {
    int i = blockIdx.x * 256 + threadIdx.x;
    if (i >= n4) return;
    float4 v = reinterpret_cast<const float4*>(in)[i];
    __half2 a = __floats2half2_rn(v.x, v.y);
    __half2 b = __floats2half2_rn(v.z, v.w);
    uint2 o;
    o.x = *reinterpret_cast<uint32_t*>(&a);
    o.y = *reinterpret_cast<uint32_t*>(&b);
    reinterpret_cast<uint2*>(out)[i] = o;
}

// ---------------------------------------------------------------------------
// Kernel 1: HMMA f16 GEMM (f16 accumulate) — R13 config (best measured:
// 358us, tensor 63.5%). CTA 128x128, 512 threads (16 warps, warp tile
// 32x32), KC=64, 3-stage cp.async. Per k16: 4 ldsm_x4 (A:2, B:2 paired).
// ---------------------------------------------------------------------------
#define KC    64
#define NIT   (DMODEL / KC)        // 16
#define ROWB  144                  // 128 B data (64 f16) + 16 B pad
#define TILEB (128 * ROWB)         // 18432
#define STAGEB (2 * TILEB)         // 36864
#define GSMEM (3 * STAGEB)         // 110592

__global__ __launch_bounds__(512, 2)
void gemm_kernel(const __half* __restrict__ A, const __half* __restrict__ B,
                 __half* __restrict__ C) {
    extern __shared__ __align__(128) char sm[];
    const uint32_t smb = smem_to_u32(sm);
    const int tid  = threadIdx.x;
    const int wid  = tid >> 5;          // 0..15
    const int lane = tid & 31;
    const int wm   = wid >> 2;          // 0..3 -> 32 rows of m
    const int wn   = wid & 3;           // 0..3 -> 32 cols of n
    const int m0   = blockIdx.y * 128;
    const int n0   = blockIdx.x * 128;

    uint32_t acc[2][4][2];
    #pragma unroll
    for (int i = 0; i < 2; i++)
        #pragma unroll
        for (int j = 0; j < 4; j++) { acc[i][j][0] = 0u; acc[i][j][1] = 0u; }

    auto load_stage = [&](int it) {
        const uint32_t aOff = smb + (it % 3) * STAGEB;
        const uint32_t bOff = aOff + TILEB;
        const int k0 = it * KC;
        #pragma unroll
        for (int i = 0; i < 2; i++) {
            int c = tid + i * 512;          // 0..1023
            int row = c >> 3;               // 0..127
            int q = c & 7;
            cp_async16(aOff + row * ROWB + q * 16,
                       A + (size_t)(m0 + row) * DMODEL + k0 + q * 8);
            cp_async16(bOff + row * ROWB + q * 16,
                       B + (size_t)(n0 + row) * DMODEL + k0 + q * 8);
        }
        CP_COMMIT();
    };

    const int arow = wm * 32 + (lane & 15);           // + mi*16
    const uint32_t a_klo = (lane >> 4) * 16;
    const int brow = wn * 32 + ((lane >> 4) << 3) + (lane & 7);   // + np*16
    const uint32_t b_klo = ((lane >> 3) & 1) * 16;

    load_stage(0);
    load_stage(1);

    for (int s = 0; s < NIT; s++) {
        if (s + 1 < NIT) { CP_WAIT(1); } else { CP_WAIT(0); }
        __syncthreads();
        if (s + 2 < NIT) load_stage(s + 2);

        const uint32_t aOff = smb + (s % 3) * STAGEB;
        const uint32_t bOff = aOff + TILEB;

        #pragma unroll
        for (int kk = 0; kk < KC; kk += 16) {
            uint32_t af[2][4], bp[2][4];
            #pragma unroll
            for (int mi = 0; mi < 2; mi++)
                ldsm_x4(af[mi], aOff + (arow + mi * 16) * ROWB + kk * 2 + a_klo);
            #pragma unroll
            for (int np = 0; np < 2; np++)
                ldsm_x4(bp[np], bOff + (brow + np * 16) * ROWB + kk * 2 + b_klo);
            #pragma unroll
            for (int mi = 0; mi < 2; mi++)
                #pragma unroll
                for (int ni = 0; ni < 4; ni++)
                    mma_f16acc(acc[mi][ni], af[mi],
                               bp[ni >> 1][(ni & 1) * 2],
                               bp[ni >> 1][(ni & 1) * 2 + 1]);
        }
    }

    #pragma unroll
    for (int mi = 0; mi < 2; mi++) {
        #pragma unroll
        for (int ni = 0; ni < 4; ni++) {
            int m = m0 + wm * 32 + mi * 16 + (lane >> 2);
            int n = n0 + wn * 32 + ni * 8 + (lane & 3) * 2;
            *reinterpret_cast<uint32_t*>(C + (size_t)m * DICT + n) = acc[mi][ni][0];
            *reinterpret_cast<uint32_t*>(C + (size_t)(m + 8) * DICT + n) = acc[mi][ni][1];
        }
    }
}

// ---------------------------------------------------------------------------
// Kernel 2: per-token top-16 — 4 tokens per block, 64 threads (2 warps)
// per token, depth-7 register lists (safe: P(thread owns >=8 of top-16)
// ~3e-9/token). Phase A: 2 warps/token produce sorted top-16 each (16
// butterfly rounds). Phase B: one thread per token does a serial 2-list
// cursor merge. Total merge instructions drop 4x vs R15.
// ---------------------------------------------------------------------------
__global__ __launch_bounds__(256)
void topc_kernel() {
    const int tid = threadIdx.x;
    const int sub = tid >> 6;            // token slot in block (0..3)
    const int g   = tid & 63;            // thread within token group
    const int token = blockIdx.x * 4 + sub;
    const int lane = tid & 31;
    const int wid  = tid >> 5;           // 0..7 (2 warps per token)
    const __half* __restrict__ row = g_ch + (size_t)token * DICT;

    const float NINF = -3.4e38f;
    float v0 = NINF, v1 = NINF, v2 = NINF, v3 = NINF, v4 = NINF, v5 = NINF, v6 = NINF;
    int   i0 = 0x7fffffff, i1 = 0x7fffffff, i2 = 0x7fffffff, i3 = 0x7fffffff,
          i4 = 0x7fffffff, i5 = 0x7fffffff, i6 = 0x7fffffff;

    // scan: 32 iterations x 8 halfs; 2048 groups split over 64 threads
    #pragma unroll 4
    for (int itr = 0; itr < 32; itr++) {
        int grp = itr * 64 + g;
        int j0 = grp * 8;
        float4 raw = reinterpret_cast<const float4*>(row)[grp];
        const __half2* h = reinterpret_cast<const __half2*>(&raw);

        __half2 m01 = __hmax2(h[0], h[1]);
        __half2 m23 = __hmax2(h[2], h[3]);
        __half2 mm  = __hmax2(m01, m23);
        float2 mf = __half22float2(mm);
        float m8 = fmaxf(mf.x, mf.y);
        if (m8 <= v6) continue;

        #pragma unroll
        for (int e = 0; e < 4; e++) {
            float2 f = __half22float2(h[e]);
            #pragma unroll
            for (int t = 0; t < 2; t++) {
                float v = t ? f.y : f.x;
                int j = j0 + e * 2 + t;
                if (v > v6) {   // branchless static insert, 7 levels
                    bool b0 = v > v0, b1 = v > v1, b2 = v > v2, b3 = v > v3,
                         b4 = v > v4, b5 = v > v5;
                    v6 = b5 ? v5 : v;              i6 = b5 ? i5 : j;
                    v5 = b5 ? (b4 ? v4 : v) : v5;  i5 = b5 ? (b4 ? i4 : j) : i5;
                    v4 = b4 ? (b3 ? v3 : v) : v4;  i4 = b4 ? (b3 ? i3 : j) : i4;
                    v3 = b3 ? (b2 ? v2 : v) : v3;  i3 = b3 ? (b2 ? i2 : j) : i3;
                    v2 = b2 ? (b1 ? v1 : v) : v2;  i2 = b2 ? (b1 ? i1 : j) : i2;
                    v1 = b1 ? (b0 ? v0 : v) : v1;  i1 = b1 ? (b0 ? i0 : j) : i1;
                    v0 = b0 ? v : v0;              i0 = b0 ? j : i0;
                }
            }
        }
    }

    // Phase A: each warp -> sorted top-16 (butterfly argmax + pop)
    __shared__ float wlv[8][TOPC];
    __shared__ int   wli[8][TOPC];

    #pragma unroll 1
    for (int r = 0; r < TOPC; r++) {
        float v = v0;
        int   i = i0;
        #pragma unroll
        for (int off = 16; off > 0; off >>= 1) {
            float ov = __shfl_xor_sync(0xffffffffu, v, off);
            int   oi = __shfl_xor_sync(0xffffffffu, i, off);
            if (ov > v || (ov == v && oi < i)) { v = ov; i = oi; }
        }
        if (lane == 0) { wlv[wid][r] = v; wli[wid][r] = i; }
        if (i0 == i) {   // winner lane pops (indices globally unique)
            v0 = v1; i0 = i1;
            v1 = v2; i1 = i2;
            v2 = v3; i2 = i3;
            v3 = v4; i3 = i4;
            v4 = v5; i4 = i5;
            v5 = v6; i5 = i6;
            v6 = NINF; i6 = 0x7fffffff;
        }
    }
    __syncthreads();

    // Phase B: serial 2-list cursor merge (one thread per token)
    if (g == 0) {
        const int wa = sub * 2, wb = sub * 2 + 1;
        int pa = 0, pb = 0;
        #pragma unroll 1
        for (int r = 0; r < TOPC; r++) {
            float va = wlv[wa][pa], vb = wlv[wb][pb];
            int   ia = wli[wa][pa], ib = wli[wb][pb];
            bool takeA = (va > vb) || (va == vb && ia < ib);
            g_cand[token * TOPC + r] = takeA ? ia : ib;
            if (takeA) pa++; else pb++;
        }
    }
}

// ---------------------------------------------------------------------------
// Kernel 3: fused exact fp32 rescore (16 candidates) + top-8 select +
// gather: offset[token][d] = sum_k v_k * W_dict[idx_k][d]   (block = token)
// ---------------------------------------------------------------------------
__global__ __launch_bounds__(256)
void rescore_gather_kernel(const float* __restrict__ x,
                           const float* __restrict__ W,
                           const float* __restrict__ Wd,
                           float* __restrict__ out) {
    const int token = blockIdx.x;
    const int tid = threadIdx.x;
    const int lane = tid & 31;
    const int wid = tid >> 5;
    __shared__ float sx[DMODEL];
    __shared__ float cv[TOPC];
    __shared__ int   ci[TOPC];
    __shared__ float sv[TOPK];
    __shared__ int   si[TOPK];

    reinterpret_cast<float4*>(sx)[tid] = reinterpret_cast<const float4*>(
        x + (size_t)token * DMODEL)[tid];
    if (tid < TOPC) ci[tid] = g_cand[token * TOPC + tid];
    __syncthreads();

    // rescore: 8 warps x 2 candidates, fp32 exact
    #pragma unroll
    for (int cc = 0; cc < 2; cc++) {
        int c = wid * 2 + cc;
        const float4* wr = reinterpret_cast<const float4*>(W + (size_t)ci[c] * DMODEL);
        const float4* sx4 = reinterpret_cast<const float4*>(sx);
        float acc = 0.f;
        #pragma unroll
        for (int i = 0; i < 8; i++) {
            float4 a = sx4[lane + i * 32];
            float4 b = wr[lane + i * 32];
            acc = fmaf(a.x, b.x, acc);
            acc = fmaf(a.y, b.y, acc);
            acc = fmaf(a.z, b.z, acc);
            acc = fmaf(a.w, b.w, acc);
        }
        #pragma unroll
        for (int off = 16; off > 0; off >>= 1)
            acc += __shfl_xor_sync(0xffffffffu, acc, off);
        if (lane == 0) cv[c] = acc;
    }
    __syncthreads();

    // top-8 select (thread 0; val desc, idx asc)
    if (tid == 0) {
        float v[TOPC]; int ix[TOPC];
        #pragma unroll
        for (int i = 0; i < TOPC; i++) { v[i] = cv[i]; ix[i] = ci[i]; }
        float run = 0.f;
        #pragma unroll
        for (int r = 0; r < TOPK; r++) {
            int best = 0;
            #pragma unroll
            for (int i = 1; i < TOPC; i++)
                if (v[i] > v[best] || (v[i] == v[best] && ix[i] < ix[best])) best = i;
            sv[r] = v[best];
            si[r] = ix[best];
            run += fabsf(v[best]);
            v[best] = -3.4e38f;
        }
        g_tokloss[token] = run;
    }
    __syncthreads();

    // gather: 4 floats per thread over DMODEL
    int d = tid * 4;
    float4 acc = make_float4(0.f, 0.f, 0.f, 0.f);
    #pragma unroll
    for (int k = 0; k < TOPK; k++) {
        const float4 w = *reinterpret_cast<const float4*>(&Wd[(size_t)si[k] * DMODEL + d]);
        float vv = sv[k];
        acc.x = fmaf(vv, w.x, acc.x);
        acc.y = fmaf(vv, w.y, acc.y);
        acc.z = fmaf(vv, w.z, acc.z);
        acc.w = fmaf(vv, w.w, acc.w);
    }
    *reinterpret_cast<float4*>(&out[(size_t)token * DMODEL + d]) = acc;
}

// ---------------------------------------------------------------------------
// Kernel 4: sparsity loss (fixed-order tree reduction)
// ---------------------------------------------------------------------------
__global__ __launch_bounds__(256)
void loss_kernel(float* __restrict__ out, int out_size) {
    __shared__ float s[256];
    float acc = 0.f;
    for (int i = threadIdx.x; i < NTOK; i += 256) acc += g_tokloss[i];
    s[threadIdx.x] = acc;
    __syncthreads();
    for (int st = 128; st > 0; st >>= 1) {
        if (threadIdx.x < st) s[threadIdx.x] += s[threadIdx.x + st];
        __syncthreads();
    }
    if (threadIdx.x == 0 && out_size > NTOK * DMODEL) {
        out[out_size - 1] = s[0] / ((float)NTOK * (float)DICT);
    }
}

// ---------------------------------------------------------------------------
extern "C" void kernel_launch(void* const* d_in, const int* in_sizes, int n_in,
                              void* d_out, int out_size) {
    const float* x      = (const float*)d_in[0];   // [4096, 1024]
    const float* W_enc  = (const float*)d_in[1];   // [16384, 1024]
    const float* W_dict = (const float*)d_in[2];   // [16384, 1024]
    float* out = (float*)d_out;

    __half *xh, *wh, *ch;
    cudaGetSymbolAddress((void**)&xh, g_xh);
    cudaGetSymbolAddress((void**)&wh, g_wh);
    cudaGetSymbolAddress((void**)&ch, g_ch);

    cudaFuncSetAttribute(gemm_kernel, cudaFuncAttributeMaxDynamicSharedMemorySize, GSMEM);

    conv_kernel<<<(NTOK * DMODEL / 4 + 255) / 256, 256>>>(x, xh, NTOK * DMODEL / 4);
    conv_kernel<<<(DICT * DMODEL / 4 + 255) / 256, 256>>>(W_enc, wh, DICT * DMODEL / 4);

    dim3 ggrid(DICT / 128, NTOK / 128);            // (128, 32)
    gemm_kernel<<<ggrid, 512, GSMEM>>>(xh, wh, ch);

    topc_kernel<<<NTOK / 4, 256>>>();              // 4th launch -> ncu slot
    rescore_gather_kernel<<<NTOK, 256>>>(x, W_enc, W_dict, out);
    loss_kernel<<<1, 256>>>(out, out_size);
}

// round 17
// speedup vs baseline: 1.0806x; 1.0806x over previous
#include <cuda_runtime.h>
#include <cuda_fp16.h>
#include <math.h>
#include <stdint.h>

// Problem constants
#define NTOK   4096
#define DMODEL 1024
#define DICT   16384
#define TOPK   8
#define TOPC   16      // candidates kept before fp32 rescore

// ---------------------------------------------------------------------------
// Scratch (__device__ globals; no allocation allowed)
// ---------------------------------------------------------------------------
__device__ __half g_xh[(size_t)NTOK * DMODEL];        // 8 MB
__device__ __half g_wh[(size_t)DICT * DMODEL];        // 32 MB
__device__ __half g_ch[(size_t)NTOK * DICT];          // 128 MB (f16 coeffs)
__device__ int   g_cand[NTOK * TOPC];
__device__ float g_vals[NTOK * TOPK];
__device__ int   g_idx[NTOK * TOPK];
__device__ float g_tokloss[NTOK];

// ---------------------------------------------------------------------------
// PTX helpers (sm_80-level; legal at virtual arch compute_103)
// ---------------------------------------------------------------------------
__device__ __forceinline__ uint32_t smem_to_u32(const void* p) {
    uint32_t a;
    asm("{ .reg .u64 t; cvta.to.shared.u64 t, %1; cvt.u32.u64 %0, t; }"
        : "=r"(a) : "l"(p));
    return a;
}
__device__ __forceinline__ void cp_async16(uint32_t dst, const void* src) {
    asm volatile("cp.async.cg.shared.global [%0], [%1], 16;" :: "r"(dst), "l"(src));
}
#define CP_COMMIT() asm volatile("cp.async.commit_group;" ::: "memory")
#define CP_WAIT(n)  asm volatile("cp.async.wait_group %0;" :: "n"(n) : "memory")

__device__ __forceinline__ void ldsm_x4(uint32_t* r, uint32_t addr) {
    asm volatile("ldmatrix.sync.aligned.m8n8.x4.shared.b16 {%0,%1,%2,%3}, [%4];"
        : "=r"(r[0]), "=r"(r[1]), "=r"(r[2]), "=r"(r[3]) : "r"(addr));
}
// f16 x f16 -> f16 accumulate (D,C are 2 regs of f16x2)
__device__ __forceinline__ void mma_f16acc(uint32_t* d, const uint32_t* a,
                                           uint32_t b0, uint32_t b1) {
    asm volatile("mma.sync.aligned.m16n8k16.row.col.f16.f16.f16.f16 "
        "{%0,%1}, {%2,%3,%4,%5}, {%6,%7}, {%0,%1};"
        : "+r"(d[0]), "+r"(d[1])
        : "r"(a[0]), "r"(a[1]), "r"(a[2]), "r"(a[3]),
          "r"(b0), "r"(b1));
}

// ---------------------------------------------------------------------------
// Kernel 0: fp32 -> f16 conversion (x and W_enc in one launch)
// ---------------------------------------------------------------------------
#define NX4 (NTOK * DMODEL / 4)
#define NW4 (DICT * DMODEL / 4)

__global__ __launch_bounds__(256)
void conv2_kernel(const float* __restrict__ x, const float* __restrict__ w,
                  __half* __restrict__ xh, __half* __restrict__ wh) {
    int i = blockIdx.x * 256 + threadIdx.x;
    const float* in;
    __half* out;
    int j;
    if (i < NX4) { in = x; out = xh; j = i; }
    else if (i < NX4 + NW4) { in = w; out = wh; j = i - NX4; }
    else return;
    float4 v = reinterpret_cast<const float4*>(in)[j];
    __half2 a = __floats2half2_rn(v.x, v.y);
    __half2 b = __floats2half2_rn(v.z, v.w);
    uint2 o;
    o.x = *reinterpret_cast<uint32_t*>(&a);
    o.y = *reinterpret_cast<uint32_t*>(&b);
    reinterpret_cast<uint2*>(out)[j] = o;
}

// ---------------------------------------------------------------------------
// Kernel 1: HMMA f16 GEMM (f16 accumulate) — R13 config (best measured:
// 358us, tensor 63.5%). CTA 128x128, 512 threads (16 warps, warp tile
// 32x32), KC=64, 3-stage cp.async. Per k16: 4 ldsm_x4 (A:2, B:2 paired).
// ---------------------------------------------------------------------------
#define KC    64
#define NIT   (DMODEL / KC)        // 16
#define ROWB  144                  // 128 B data (64 f16) + 16 B pad
#define TILEB (128 * ROWB)         // 18432
#define STAGEB (2 * TILEB)         // 36864
#define GSMEM (3 * STAGEB)         // 110592

__global__ __launch_bounds__(512, 2)
void gemm_kernel(const __half* __restrict__ A, const __half* __restrict__ B,
                 __half* __restrict__ C) {
    extern __shared__ __align__(128) char sm[];
    const uint32_t smb = smem_to_u32(sm);
    const int tid  = threadIdx.x;
    const int wid  = tid >> 5;          // 0..15
    const int lane = tid & 31;
    const int wm   = wid >> 2;          // 0..3 -> 32 rows of m
    const int wn   = wid & 3;           // 0..3 -> 32 cols of n
    const int m0   = blockIdx.y * 128;
    const int n0   = blockIdx.x * 128;

    uint32_t acc[2][4][2];
    #pragma unroll
    for (int i = 0; i < 2; i++)
        #pragma unroll
        for (int j = 0; j < 4; j++) { acc[i][j][0] = 0u; acc[i][j][1] = 0u; }

    auto load_stage = [&](int it) {
        const uint32_t aOff = smb + (it % 3) * STAGEB;
        const uint32_t bOff = aOff + TILEB;
        const int k0 = it * KC;
        #pragma unroll
        for (int i = 0; i < 2; i++) {
            int c = tid + i * 512;          // 0..1023
            int row = c >> 3;               // 0..127
            int q = c & 7;
            cp_async16(aOff + row * ROWB + q * 16,
                       A + (size_t)(m0 + row) * DMODEL + k0 + q * 8);
            cp_async16(bOff + row * ROWB + q * 16,
                       B + (size_t)(n0 + row) * DMODEL + k0 + q * 8);
        }
        CP_COMMIT();
    };

    const int arow = wm * 32 + (lane & 15);           // + mi*16
    const uint32_t a_klo = (lane >> 4) * 16;
    const int brow = wn * 32 + ((lane >> 4) << 3) + (lane & 7);   // + np*16
    const uint32_t b_klo = ((lane >> 3) & 1) * 16;

    load_stage(0);
    load_stage(1);

    for (int s = 0; s < NIT; s++) {
        if (s + 1 < NIT) { CP_WAIT(1); } else { CP_WAIT(0); }
        __syncthreads();
        if (s + 2 < NIT) load_stage(s + 2);

        const uint32_t aOff = smb + (s % 3) * STAGEB;
        const uint32_t bOff = aOff + TILEB;

        #pragma unroll
        for (int kk = 0; kk < KC; kk += 16) {
            uint32_t af[2][4], bp[2][4];
            #pragma unroll
            for (int mi = 0; mi < 2; mi++)
                ldsm_x4(af[mi], aOff + (arow + mi * 16) * ROWB + kk * 2 + a_klo);
            #pragma unroll
            for (int np = 0; np < 2; np++)
                ldsm_x4(bp[np], bOff + (brow + np * 16) * ROWB + kk * 2 + b_klo);
            #pragma unroll
            for (int mi = 0; mi < 2; mi++)
                #pragma unroll
                for (int ni = 0; ni < 4; ni++)
                    mma_f16acc(acc[mi][ni], af[mi],
                               bp[ni >> 1][(ni & 1) * 2],
                               bp[ni >> 1][(ni & 1) * 2 + 1]);
        }
    }

    #pragma unroll
    for (int mi = 0; mi < 2; mi++) {
        #pragma unroll
        for (int ni = 0; ni < 4; ni++) {
            int m = m0 + wm * 32 + mi * 16 + (lane >> 2);
            int n = n0 + wn * 32 + ni * 8 + (lane & 3) * 2;
            *reinterpret_cast<uint32_t*>(C + (size_t)m * DICT + n) = acc[mi][ni][0];
            *reinterpret_cast<uint32_t*>(C + (size_t)(m + 8) * DICT + n) = acc[mi][ni][1];
        }
    }
}

// ---------------------------------------------------------------------------
// Kernel 2: per-token top-16 — packed-key top-k.
// key = sortkey16(f16) << 14 | (0x3FFF ^ idx): value desc + idx asc in one
// u32 compare. Scan keeps a depth-5 key list (safe: P(elem lost) =
// C(15,5)/256^5 * 16 * 4096 ~ 2e-4). Merge rounds use __reduce_max_sync
// (REDUX) instead of 5-shuffle butterflies; pops are single-key shifts.
// g_cand order is irrelevant: rescore re-ranks all 16 in fp32.
// ---------------------------------------------------------------------------
__global__ __launch_bounds__(256)
void topc_kernel() {
    const int token = blockIdx.x;
    const __half* __restrict__ row = g_ch + (size_t)token * DICT;
    const int tid = threadIdx.x;
    const int lane = tid & 31;
    const int wid = tid >> 5;

    uint32_t k0 = 0, k1 = 0, k2 = 0, k3 = 0, k4 = 0;   // 0 = sentinel (< any real key)

    #pragma unroll
    for (int itr = 0; itr < 8; itr++) {
        int j0 = (itr * 256 + tid) * 8;
        float4 raw = *reinterpret_cast<const float4*>(row + j0);
        const __half2* h = reinterpret_cast<const __half2*>(&raw);
        const uint32_t* p = reinterpret_cast<const uint32_t*>(&raw);

        // prescreen in half domain: max of 8
        __half2 m01 = __hmax2(h[0], h[1]);
        __half2 m23 = __hmax2(h[2], h[3]);
        __half2 mm  = __hmax2(m01, m23);
        __half  hm  = __hmax(__low2half(mm), __high2half(mm));
        uint32_t hb = (uint32_t)__half_as_ushort(hm);
        uint32_t mk = hb ^ (0x8000u | ((hb >> 15) * 0x7FFFu));   // sortable u16
        if (((mk << 14) | 0x3FFFu) <= k4) continue;   // even best idx can't enter

        // transform the 4 f16x2 pairs to sortable key16 pairs (3 ops each)
        #pragma unroll
        for (int e = 0; e < 4; e++) {
            uint32_t kp = p[e] ^ (0x80008000u |
                          (((p[e] >> 15) & 0x10001u) * 0x7FFFu));
            #pragma unroll
            for (int t = 0; t < 2; t++) {
                uint32_t k16 = t ? (kp >> 16) : (kp & 0xFFFFu);
                uint32_t key = (k16 << 14) | (0x3FFFu ^ (uint32_t)(j0 + e * 2 + t));
                if (key > k4) {   // branchless static insert, 5 levels, keys only
                    bool b0 = key > k0, b1 = key > k1, b2 = key > k2, b3 = key > k3;
                    k4 = b3 ? k3 : key;
                    k3 = b3 ? (b2 ? k2 : key) : k3;
                    k2 = b2 ? (b1 ? k1 : key) : k2;
                    k1 = b1 ? (b0 ? k0 : key) : k1;
                    k0 = b0 ? key : k0;
                }
            }
        }
    }

    // Phase A: each warp -> its top-16 keys via REDUX rounds (barrier-free)
    __shared__ uint32_t wl[8][TOPC];

    #pragma unroll 1
    for (int r = 0; r < TOPC; r++) {
        uint32_t win = __reduce_max_sync(0xffffffffu, k0);
        if (lane == 0) wl[wid][r] = win;
        if (k0 == win) {   // keys unique (idx in low bits) -> exactly one pops
            k0 = k1; k1 = k2; k2 = k3; k3 = k4; k4 = 0;
        }
    }
    __syncthreads();

    // Phase B: warp 0 merges 8 sorted lists via 8 lane-cursors + REDUX
    if (wid == 0) {
        int p = 0;
        #pragma unroll 1
        for (int r = 0; r < TOPC; r++) {
            uint32_t v = (lane < 8) ? wl[lane][p] : 0u;
            uint32_t win = __reduce_max_sync(0xffffffffu, v);
            if (lane == 0)
                g_cand[token * TOPC + r] = (int)(0x3FFFu ^ (win & 0x3FFFu));
            if (lane < 8 && v == win) p++;
        }
    }
}

// ---------------------------------------------------------------------------
// Kernel 3: exact fp32 rescore of 16 candidates + top-8 select (block = token)
// ---------------------------------------------------------------------------
__global__ __launch_bounds__(256)
void rescore_kernel(const float* __restrict__ x, const float* __restrict__ W) {
    const int token = blockIdx.x;
    const int tid = threadIdx.x;
    const int lane = tid & 31;
    const int wid = tid >> 5;
    __shared__ float sx[DMODEL];
    __shared__ float cv[TOPC];
    __shared__ int   ci[TOPC];

    reinterpret_cast<float4*>(sx)[tid] = reinterpret_cast<const float4*>(
        x + (size_t)token * DMODEL)[tid];
    if (tid < TOPC) ci[tid] = g_cand[token * TOPC + tid];
    __syncthreads();

    #pragma unroll
    for (int cc = 0; cc < 2; cc++) {
        int c = wid * 2 + cc;
        const float4* wr = reinterpret_cast<const float4*>(W + (size_t)ci[c] * DMODEL);
        const float4* sx4 = reinterpret_cast<const float4*>(sx);
        float acc = 0.f;
        #pragma unroll
        for (int i = 0; i < 8; i++) {
            float4 a = sx4[lane + i * 32];
            float4 b = wr[lane + i * 32];
            acc = fmaf(a.x, b.x, acc);
            acc = fmaf(a.y, b.y, acc);
            acc = fmaf(a.z, b.z, acc);
            acc = fmaf(a.w, b.w, acc);
        }
        #pragma unroll
        for (int off = 16; off > 0; off >>= 1)
            acc += __shfl_xor_sync(0xffffffffu, acc, off);
        if (lane == 0) cv[c] = acc;
    }
    __syncthreads();

    if (tid == 0) {
        float v[TOPC]; int ix[TOPC];
        #pragma unroll
        for (int i = 0; i < TOPC; i++) { v[i] = cv[i]; ix[i] = ci[i]; }
        float run = 0.f;
        #pragma unroll
        for (int r = 0; r < TOPK; r++) {
            int best = 0;
            #pragma unroll
            for (int i = 1; i < TOPC; i++)
                if (v[i] > v[best] || (v[i] == v[best] && ix[i] < ix[best])) best = i;
            g_vals[token * TOPK + r] = v[best];
            g_idx[token * TOPK + r]  = ix[best];
            run += fabsf(v[best]);
            v[best] = -3.4e38f;
        }
        g_tokloss[token] = run;
    }
}

// ---------------------------------------------------------------------------
// Kernel 4: offset[token][d] = sum_k v_k * W_dict[idx_k][d]
// ---------------------------------------------------------------------------
__global__ __launch_bounds__(256)
void gather_kernel(const float* __restrict__ Wd, float* __restrict__ out) {
    const int token = blockIdx.x;
    const int tid = threadIdx.x;
    __shared__ float sv[TOPK];
    __shared__ int   si[TOPK];
    if (tid < TOPK) { sv[tid] = g_vals[token * TOPK + tid]; si[tid] = g_idx[token * TOPK + tid]; }
    __syncthreads();

    int d = tid * 4;
    float4 acc = make_float4(0.f, 0.f, 0.f, 0.f);
    #pragma unroll
    for (int k = 0; k < TOPK; k++) {
        const float4 w = *reinterpret_cast<const float4*>(&Wd[(size_t)si[k] * DMODEL + d]);
        float v = sv[k];
        acc.x = fmaf(v, w.x, acc.x);
        acc.y = fmaf(v, w.y, acc.y);
        acc.z = fmaf(v, w.z, acc.z);
        acc.w = fmaf(v, w.w, acc.w);
    }
    *reinterpret_cast<float4*>(&out[(size_t)token * DMODEL + d]) = acc;
}

// ---------------------------------------------------------------------------
// Kernel 5: sparsity loss (fixed-order tree reduction)
// ---------------------------------------------------------------------------
__global__ __launch_bounds__(256)
void loss_kernel(float* __restrict__ out, int out_size) {
    __shared__ float s[256];
    float acc = 0.f;
    for (int i = threadIdx.x; i < NTOK; i += 256) acc += g_tokloss[i];
    s[threadIdx.x] = acc;
    __syncthreads();
    for (int st = 128; st > 0; st >>= 1) {
        if (threadIdx.x < st) s[threadIdx.x] += s[threadIdx.x + st];
        __syncthreads();
    }
    if (threadIdx.x == 0 && out_size > NTOK * DMODEL) {
        out[out_size - 1] = s[0] / ((float)NTOK * (float)DICT);
    }
}

// ---------------------------------------------------------------------------
extern "C" void kernel_launch(void* const* d_in, const int* in_sizes, int n_in,
                              void* d_out, int out_size) {
    const float* x      = (const float*)d_in[0];   // [4096, 1024]
    const float* W_enc  = (const float*)d_in[1];   // [16384, 1024]
    const float* W_dict = (const float*)d_in[2];   // [16384, 1024]
    float* out = (float*)d_out;

    __half *xh, *wh, *ch;
    cudaGetSymbolAddress((void**)&xh, g_xh);
    cudaGetSymbolAddress((void**)&wh, g_wh);
    cudaGetSymbolAddress((void**)&ch, g_ch);

    cudaFuncSetAttribute(gemm_kernel, cudaFuncAttributeMaxDynamicSharedMemorySize, GSMEM);

    conv2_kernel<<<(NX4 + NW4 + 255) / 256, 256>>>(x, W_enc, xh, wh);

    dim3 ggrid(DICT / 128, NTOK / 128);            // (128, 32)
    gemm_kernel<<<ggrid, 512, GSMEM>>>(xh, wh, ch);

    topc_kernel<<<NTOK, 256>>>();
    rescore_kernel<<<NTOK, 256>>>(x, W_enc);
    gather_kernel<<<NTOK, 256>>>(W_dict, out);
    loss_kernel<<<1, 256>>>(out, out_size);
}